// round 11
// baseline (speedup 1.0000x reference)
#include <cuda_runtime.h>
#include <cstdint>

#define ROWS_TOTAL 32768
#define DIM 768
#define NF 16
#define NQ 8

/* ---------- kernel 1 : eighth-K GEMM, 4 rows/thread, 4 blocks/SM ---------- */
#define BLOCK 128
#define RPT 4
#define ROWS_PB 512
#define NSPLIT 8
#define KE 96                         /* K eighth */
#define KB 8                          /* k per chunk */
#define NCHUNK (KE / KB)              /* 12 */
#define LDX 12                        /* 8 + 4 pad, conflict-free */
#define WE_FLOATS (KE * NF)           /* 1536 = 6KB */
#define XBUF_FLOATS (ROWS_PB * LDX)   /* 6144 = 24KB */
#define SMEM_BYTES ((WE_FLOATS + 2 * XBUF_FLOATS) * 4)  /* 55296 -> 4 blocks/SM */

__device__ float g_part[NSPLIT][ROWS_TOTAL * NF];   /* 16MB scratch */

__device__ __forceinline__ void ffma2(unsigned long long &d,
                                      unsigned long long a,
                                      unsigned long long b) {
    asm("fma.rn.f32x2 %0, %1, %2, %0;" : "+l"(d) : "l"(a), "l"(b));
}

__device__ __forceinline__ unsigned long long splat(float v) {
    unsigned long long r;
    asm("mov.b64 %0, {%1, %1};" : "=l"(r) : "f"(v));
    return r;
}

__device__ __forceinline__ void cp_async16(float* dst, const float* src) {
    unsigned int d = (unsigned int)__cvta_generic_to_shared(dst);
    asm volatile("cp.async.cg.shared.global [%0], [%1], 16;" :: "r"(d), "l"(src));
}

/* stage one 512-row x 8-k chunk: 1024 x 16B, 8 per thread */
__device__ __forceinline__ void stage_x(const float* __restrict__ xe,
                                        float* __restrict__ dst,
                                        int c, int tid) {
    #pragma unroll
    for (int t = 0; t < 8; t++) {
        int idx = t * BLOCK + tid;
        int h = idx & 1, row = idx >> 1;
        cp_async16(dst + row * LDX + h * 4,
                   xe + (size_t)row * DIM + c * KB + h * 4);
    }
    asm volatile("cp.async.commit_group;");
}

__global__ __launch_bounds__(BLOCK, 4)
void qadapter_gemm(const float* __restrict__ x,
                   const float* __restrict__ W) {
    extern __shared__ float smem[];
    float* W_s = smem;                 /* 1536 floats */
    float* x_s = smem + WE_FLOATS;     /* 2 x 6144 floats */

    const int tid  = threadIdx.x;
    const int e    = blockIdx.x & 7;
    const int base = (blockIdx.x >> 3) * ROWS_PB;
    const float* xe = x + (size_t)base * DIM + e * KE;

    /* stage this eighth's W : group 0 (384 float4, 3 per thread) */
    {
        const float4* Wsrc = reinterpret_cast<const float4*>(W + e * KE * NF);
        #pragma unroll
        for (int i = 0; i < 3; i++) {
            int g4 = i * BLOCK + tid;
            cp_async16(W_s + g4 * 4, reinterpret_cast<const float*>(Wsrc + g4));
        }
        asm volatile("cp.async.commit_group;");
    }
    stage_x(xe, x_s, 0, tid);                 /* group 1 */
    stage_x(xe, x_s + XBUF_FLOATS, 1, tid);   /* group 2 */

    unsigned long long acc[RPT][8];
    #pragma unroll
    for (int j = 0; j < RPT; j++)
        #pragma unroll
        for (int i = 0; i < 8; i++) acc[j][i] = 0ull;

    for (int ch = 0; ch < NCHUNK; ch++) {
        if (ch < NCHUNK - 1) asm volatile("cp.async.wait_group 1;");
        else                 asm volatile("cp.async.wait_group 0;");
        __syncthreads();

        const float* xr = x_s + (ch & 1) * XBUF_FLOATS + tid * LDX;
        const float* wc = W_s + ch * (KB * NF);

        #pragma unroll
        for (int kk = 0; kk < KB; kk += 4) {
            float4 xv[RPT];
            #pragma unroll
            for (int j = 0; j < RPT; j++)
                xv[j] = *reinterpret_cast<const float4*>(
                    xr + j * (BLOCK * LDX) + kk);
            const float xe4[RPT][4] = {
                {xv[0].x, xv[0].y, xv[0].z, xv[0].w},
                {xv[1].x, xv[1].y, xv[1].z, xv[1].w},
                {xv[2].x, xv[2].y, xv[2].z, xv[2].w},
                {xv[3].x, xv[3].y, xv[3].z, xv[3].w}};
            #pragma unroll
            for (int kj = 0; kj < 4; kj++) {
                const ulonglong2* wp = reinterpret_cast<const ulonglong2*>(
                    wc + (kk + kj) * NF);
                ulonglong2 w01 = wp[0];   /* full-warp broadcast LDS.128 */
                ulonglong2 w23 = wp[1];
                ulonglong2 w45 = wp[2];
                ulonglong2 w67 = wp[3];
                #pragma unroll
                for (int j = 0; j < RPT; j++) {
                    unsigned long long xs = splat(xe4[j][kj]);
                    ffma2(acc[j][0], xs, w01.x);
                    ffma2(acc[j][1], xs, w01.y);
                    ffma2(acc[j][2], xs, w23.x);
                    ffma2(acc[j][3], xs, w23.y);
                    ffma2(acc[j][4], xs, w45.x);
                    ffma2(acc[j][5], xs, w45.y);
                    ffma2(acc[j][6], xs, w67.x);
                    ffma2(acc[j][7], xs, w67.y);
                }
            }
        }
        __syncthreads();
        if (ch + 2 < NCHUNK)
            stage_x(xe, x_s + (ch & 1) * XBUF_FLOATS, ch + 2, tid);
    }

    /* write fp32 partials for 4 rows */
    #pragma unroll
    for (int j = 0; j < RPT; j++) {
        float4* dst = reinterpret_cast<float4*>(
            &g_part[e][(size_t)(base + tid + j * BLOCK) * NF]);
        #pragma unroll
        for (int i = 0; i < 4; i++) {
            float a  = __uint_as_float((unsigned int)(acc[j][2 * i] & 0xffffffffull));
            float bb = __uint_as_float((unsigned int)(acc[j][2 * i] >> 32));
            float c  = __uint_as_float((unsigned int)(acc[j][2 * i + 1] & 0xffffffffull));
            float d  = __uint_as_float((unsigned int)(acc[j][2 * i + 1] >> 32));
            dst[i] = make_float4(a, bb, c, d);
        }
    }
}

/* ---------- kernel 2 : combine 8 partials, 4 threads/row ---------- */
__global__ __launch_bounds__(256)
void qadapter_epi(const float* __restrict__ b,
                  const float* __restrict__ enc,
                  float* __restrict__ out) {
    const int idx = blockIdx.x * 256 + threadIdx.x;   /* 131072 total */
    const int row = idx >> 2;
    const int cg  = idx & 3;                          /* col group: cols 4cg.. */
    const size_t off = (size_t)row * NF + cg * 4;

    float4 p[NSPLIT];
    #pragma unroll
    for (int e = 0; e < NSPLIT; e++)
        p[e] = *reinterpret_cast<const float4*>(&g_part[e][off]);

    float4 s4 = p[0];
    #pragma unroll
    for (int e = 1; e < NSPLIT; e++) {
        s4.x += p[e].x; s4.y += p[e].y; s4.z += p[e].z; s4.w += p[e].w;
    }

    float z0 = s4.x + __ldg(&b[4 * cg]);
    float z1 = s4.y + __ldg(&b[4 * cg + 1]);
    float z2 = s4.z + __ldg(&b[4 * cg + 2]);
    float z3 = s4.w + __ldg(&b[4 * cg + 3]);
    float e0 = __expf(2.0f * z0), e1 = __expf(2.0f * z1);
    float e2 = __expf(2.0f * z2), e3 = __expf(2.0f * z3);
    float t0 = __fdividef(e0 - 1.0f, e0 + 1.0f);
    float t1 = __fdividef(e1 - 1.0f, e1 + 1.0f);
    float t2 = __fdividef(e2 - 1.0f, e2 + 1.0f);
    float t3 = __fdividef(e3 - 1.0f, e3 + 1.0f);

    /* cols 4cg..4cg+3 = qubits 2cg (t0,t1), 2cg+1 (t2,t3) */
    int q0 = 2 * cg, q1 = 2 * cg + 1;
    float th0 = t0 + __ldg(&enc[q0 * 3 + 0]);
    float ph0 = t1 + __ldg(&enc[q0 * 3 + 1]);
    float th1 = t2 + __ldg(&enc[q1 * 3 + 0]);
    float ph1 = t3 + __ldg(&enc[q1 * 3 + 1]);
    float sn0, cs0, sn1, cs1;
    __sincosf(0.5f * th0, &sn0, &cs0);
    __sincosf(0.5f * th1, &sn1, &cs1);
    float4 o = make_float4(cs0, sn0 * __cosf(ph0), cs1, sn1 * __cosf(ph1));
    *reinterpret_cast<float4*>(out + off) = o;
}

extern "C" void kernel_launch(void* const* d_in, const int* in_sizes, int n_in,
                              void* d_out, int out_size) {
    const float* x   = (const float*)d_in[0];
    const float* W   = (const float*)d_in[1];
    const float* b   = (const float*)d_in[2];
    const float* enc = (const float*)d_in[3];
    float* out = (float*)d_out;

    cudaFuncSetAttribute(qadapter_gemm,
                         cudaFuncAttributeMaxDynamicSharedMemorySize, SMEM_BYTES);
    qadapter_gemm<<<(ROWS_TOTAL / ROWS_PB) * NSPLIT, BLOCK, SMEM_BYTES>>>(x, W);
    qadapter_epi<<<(ROWS_TOTAL * 4) / 256, 256>>>(b, enc, out);
}